// round 5
// baseline (speedup 1.0000x reference)
#include <cuda_runtime.h>
#include <cuda_bf16.h>
#include <cstdint>

// GINConv (max agg, eps=0) + MLP.
// R5: 4-edge-concurrent gather (4 groups of 8 lanes, 2 float4/lane),
//     direct bucketing, FFMA2 packed GEMM.
// Inputs: h[N*64] f32, src[E] i32, dst[E] i32, W1[64*64] f32, W2[64*64] f32, b2[64] f32.
// Output: out[N*64] f32.

#define D 64
#define NMAX 100000
#define CAP 96
#define NODES_PB 64
#define NEG_INF __int_as_float(0xff800000)

__device__ int g_cnt[NMAX];
__device__ int g_bucket[NMAX * CAP];

// ---------------- packed fp32x2 helpers (Blackwell FFMA2) ----------------
__device__ __forceinline__ void ffma2(unsigned long long& d,
                                      unsigned long long a,
                                      unsigned long long b) {
    asm("fma.rn.f32x2 %0, %1, %2, %0;" : "+l"(d) : "l"(a), "l"(b));
}
__device__ __forceinline__ unsigned long long dup2(float x) {
    unsigned long long r;
    asm("mov.b64 %0, {%1, %1};" : "=l"(r) : "f"(x));
    return r;
}
__device__ __forceinline__ float2 unpack2(unsigned long long v) {
    float2 r;
    asm("mov.b64 {%0, %1}, %2;" : "=f"(r.x), "=f"(r.y) : "l"(v));
    return r;
}

__global__ void k_zero(int n) {
    int i = blockIdx.x * blockDim.x + threadIdx.x;
    if (i < n) g_cnt[i] = 0;
}

// 2 edges per thread, vectorized index loads
__global__ void k_scatter(const int* __restrict__ src, const int* __restrict__ dst, int E) {
    int i = blockIdx.x * blockDim.x + threadIdx.x;
    int e = i * 2;
    if (e + 1 < E) {
        int2 s = *(const int2*)&src[e];
        int2 d = *(const int2*)&dst[e];
        int p0 = atomicAdd(&g_cnt[d.x], 1);
        int p1 = atomicAdd(&g_cnt[d.y], 1);
        if (p0 < CAP) g_bucket[d.x * CAP + p0] = s.x;
        if (p1 < CAP) g_bucket[d.y * CAP + p1] = s.y;
    } else if (e < E) {
        int v = dst[e];
        int pos = atomicAdd(&g_cnt[v], 1);
        if (pos < CAP) g_bucket[v * CAP + pos] = src[e];
    }
}

__device__ __forceinline__ float4 fmax4(float4 a, float4 b) {
    a.x = fmaxf(a.x, b.x); a.y = fmaxf(a.y, b.y);
    a.z = fmaxf(a.z, b.z); a.w = fmaxf(a.w, b.w);
    return a;
}
__device__ __forceinline__ void xormax4(float4& a, int m) {
    a.x = fmaxf(a.x, __shfl_xor_sync(0xffffffffu, a.x, m));
    a.y = fmaxf(a.y, __shfl_xor_sync(0xffffffffu, a.y, m));
    a.z = fmaxf(a.z, __shfl_xor_sync(0xffffffffu, a.z, m));
    a.w = fmaxf(a.w, __shfl_xor_sync(0xffffffffu, a.w, m));
}

// ---------------- fused gather-max + 2-layer MLP ----------------
// 256 threads, 64 nodes/block.
// Phase A: warp aggregates 8 nodes sequentially; per node, 4 groups of 8
//   lanes each stream one edge (2xfloat4 per lane covers 256B row) ->
//   4 concurrent edge chains, 16 loads in flight per warp.
// Phase B: two 64x64 GEMMs with packed f32x2 FMAs.
__global__ __launch_bounds__(256) void k_fused(const float* __restrict__ h,
                                               const float* __restrict__ W1,
                                               const float* __restrict__ W2,
                                               const float* __restrict__ b2,
                                               float* __restrict__ out,
                                               int nNodes) {
    __shared__ float sW[D * 66];
    __shared__ float sX[NODES_PB][D + 1];

    const int tid  = threadIdx.x;
    const int lane = tid & 31;
    const int warp = tid >> 5;
    const int grp  = lane >> 3;     // edge group 0..3
    const int sub  = lane & 7;      // float4 index within half-row
    const int n0   = blockIdx.x * NODES_PB;
    const float4* __restrict__ h4 = (const float4*)h;

    for (int t = tid; t < D * D; t += 256) {
        int j = t >> 6, k = t & 63;
        sW[k * 66 + j] = W1[t];
    }

#pragma unroll 1
    for (int r = 0; r < 8; r++) {
        int n = warp * 8 + r;
        int node = n0 + n;
        bool valid = node < nNodes;
        int deg = valid ? min(g_cnt[node], CAP) : 0;
        const int off = node * CAP;
        float4 acc0 = make_float4(NEG_INF, NEG_INF, NEG_INF, NEG_INF);
        float4 acc1 = acc0;
        for (int b = 0; b < deg; b += 32) {
            int cnt = min(32, deg - b);             // >= 1
            int sIdx = g_bucket[off + b + min(lane, cnt - 1)];
#pragma unroll 4
            for (int e = 0; e < cnt; e += 4) {
                int idx = min(e + grp, cnt - 1);     // clamp: repeat last edge (max-idempotent)
                int s = __shfl_sync(0xffffffffu, sIdx, idx);
                float4 v0 = __ldg(&h4[s * 16 + sub]);
                float4 v1 = __ldg(&h4[s * 16 + 8 + sub]);
                acc0 = fmax4(acc0, v0);
                acc1 = fmax4(acc1, v1);
            }
        }
        // combine the 4 edge groups
        xormax4(acc0, 8);  xormax4(acc0, 16);
        xormax4(acc1, 8);  xormax4(acc1, 16);
        if (deg == 0) {
            acc0 = make_float4(0.f, 0.f, 0.f, 0.f);
            acc1 = acc0;
        }
        if (grp == 0) {   // lanes 0-7 write all 64 feats
            float4 b0 = valid ? __ldg(&h4[node * 16 + sub])     : make_float4(0,0,0,0);
            float4 b1 = valid ? __ldg(&h4[node * 16 + 8 + sub]) : make_float4(0,0,0,0);
            int c0 = 4 * sub, c1 = 32 + 4 * sub;
            sX[n][c0 + 0] = valid ? b0.x + acc0.x : 0.f;
            sX[n][c0 + 1] = valid ? b0.y + acc0.y : 0.f;
            sX[n][c0 + 2] = valid ? b0.z + acc0.z : 0.f;
            sX[n][c0 + 3] = valid ? b0.w + acc0.w : 0.f;
            sX[n][c1 + 0] = valid ? b1.x + acc1.x : 0.f;
            sX[n][c1 + 1] = valid ? b1.y + acc1.y : 0.f;
            sX[n][c1 + 2] = valid ? b1.z + acc1.z : 0.f;
            sX[n][c1 + 3] = valid ? b1.w + acc1.w : 0.f;
        }
    }
    __syncthreads();

    const int tn = (tid & 15) * 4;
    const int tj = (tid >> 4) * 4;

    // ---- layer 1: y = relu(x @ W1^T), packed f32x2 ----
    unsigned long long a01[4] = {0ull, 0ull, 0ull, 0ull};
    unsigned long long a23[4] = {0ull, 0ull, 0ull, 0ull};

#pragma unroll 8
    for (int k = 0; k < D; k++) {
        const unsigned long long W01 = *(const unsigned long long*)&sW[k * 66 + tj];
        const unsigned long long W23 = *(const unsigned long long*)&sW[k * 66 + tj + 2];
#pragma unroll
        for (int nn = 0; nn < 4; nn++) {
            unsigned long long xx = dup2(sX[tn + nn][k]);
            ffma2(a01[nn], xx, W01);
            ffma2(a23[nn], xx, W23);
        }
    }
    __syncthreads();

#pragma unroll
    for (int nn = 0; nn < 4; nn++) {
        float2 p = unpack2(a01[nn]);
        float2 q = unpack2(a23[nn]);
        sX[tn + nn][tj + 0] = fmaxf(p.x, 0.f);
        sX[tn + nn][tj + 1] = fmaxf(p.y, 0.f);
        sX[tn + nn][tj + 2] = fmaxf(q.x, 0.f);
        sX[tn + nn][tj + 3] = fmaxf(q.y, 0.f);
    }
    for (int t = tid; t < D * D; t += 256) {
        int j = t >> 6, k = t & 63;
        sW[k * 66 + j] = W2[t];
    }
    __syncthreads();

    // ---- layer 2 ----
#pragma unroll
    for (int nn = 0; nn < 4; nn++) { a01[nn] = 0ull; a23[nn] = 0ull; }

#pragma unroll 8
    for (int k = 0; k < D; k++) {
        const unsigned long long W01 = *(const unsigned long long*)&sW[k * 66 + tj];
        const unsigned long long W23 = *(const unsigned long long*)&sW[k * 66 + tj + 2];
#pragma unroll
        for (int nn = 0; nn < 4; nn++) {
            unsigned long long yy = dup2(sX[tn + nn][k]);
            ffma2(a01[nn], yy, W01);
            ffma2(a23[nn], yy, W23);
        }
    }

    float4 bias = *reinterpret_cast<const float4*>(&b2[tj]);
#pragma unroll
    for (int nn = 0; nn < 4; nn++) {
        int node = n0 + tn + nn;
        if (node < nNodes) {
            float2 p = unpack2(a01[nn]);
            float2 q = unpack2(a23[nn]);
            float4 rr;
            rr.x = p.x + bias.x;
            rr.y = p.y + bias.y;
            rr.z = q.x + bias.z;
            rr.w = q.y + bias.w;
            *reinterpret_cast<float4*>(&out[node * D + tj]) = rr;
        }
    }
}

extern "C" void kernel_launch(void* const* d_in, const int* in_sizes, int n_in,
                              void* d_out, int out_size) {
    const float* h   = (const float*)d_in[0];
    const int*   src = (const int*)d_in[1];
    const int*   dst = (const int*)d_in[2];
    const float* W1  = (const float*)d_in[3];
    const float* W2  = (const float*)d_in[4];
    const float* b2  = (const float*)d_in[5];
    float* out = (float*)d_out;

    const int nNodes = in_sizes[0] / D;
    const int E      = in_sizes[1];

    k_zero<<<(nNodes + 255) / 256, 256>>>(nNodes);
    int pairs = (E + 1) / 2;
    k_scatter<<<(pairs + 255) / 256, 256>>>(src, dst, E);
    k_fused<<<(nNodes + NODES_PB - 1) / NODES_PB, 256>>>(h, W1, W2, b2, out, nNodes);
}

// round 6
// speedup vs baseline: 1.0297x; 1.0297x over previous
#include <cuda_runtime.h>
#include <cuda_bf16.h>
#include <cstdint>

// GINConv (max agg, eps=0) + MLP.
// R6: 2 launches. Direct bucketing (g_cnt self-resets inside k_fused so no
// zeroing kernel is needed), half-warp float4 gather, FFMA2 packed GEMM.
// Inputs: h[N*64] f32, src[E] i32, dst[E] i32, W1[64*64] f32, W2[64*64] f32, b2[64] f32.
// Output: out[N*64] f32.

#define D 64
#define NMAX 100000
#define CAP 96
#define NODES_PB 64
#define NEG_INF __int_as_float(0xff800000)

__device__ int g_cnt[NMAX];               // zero-initialized at load; invariant: ==0 at launch entry
__device__ int g_bucket[NMAX * CAP];

// ---------------- packed fp32x2 helpers (Blackwell FFMA2) ----------------
__device__ __forceinline__ void ffma2(unsigned long long& d,
                                      unsigned long long a,
                                      unsigned long long b) {
    asm("fma.rn.f32x2 %0, %1, %2, %0;" : "+l"(d) : "l"(a), "l"(b));
}
__device__ __forceinline__ unsigned long long dup2(float x) {
    unsigned long long r;
    asm("mov.b64 %0, {%1, %1};" : "=l"(r) : "f"(x));
    return r;
}
__device__ __forceinline__ float2 unpack2(unsigned long long v) {
    float2 r;
    asm("mov.b64 {%0, %1}, %2;" : "=f"(r.x), "=f"(r.y) : "l"(v));
    return r;
}

// ---------------- K1: scatter src ids into per-dst buckets ----------------
__global__ void k_scatter(const int* __restrict__ src, const int* __restrict__ dst, int E) {
    int i = blockIdx.x * blockDim.x + threadIdx.x;
    int e = i * 2;
    if (e + 1 < E) {
        int2 s = *(const int2*)&src[e];
        int2 d = *(const int2*)&dst[e];
        int p0 = atomicAdd(&g_cnt[d.x], 1);
        int p1 = atomicAdd(&g_cnt[d.y], 1);
        if (p0 < CAP) g_bucket[d.x * CAP + p0] = s.x;
        if (p1 < CAP) g_bucket[d.y * CAP + p1] = s.y;
    } else if (e < E) {
        int v = dst[e];
        int pos = atomicAdd(&g_cnt[v], 1);
        if (pos < CAP) g_bucket[v * CAP + pos] = src[e];
    }
}

__device__ __forceinline__ float4 fmax4(float4 a, float4 b) {
    a.x = fmaxf(a.x, b.x); a.y = fmaxf(a.y, b.y);
    a.z = fmaxf(a.z, b.z); a.w = fmaxf(a.w, b.w);
    return a;
}

// ---------------- K2: fused gather-max + 2-layer MLP (+ counter reset) ----------------
__global__ __launch_bounds__(256) void k_fused(const float* __restrict__ h,
                                               const float* __restrict__ W1,
                                               const float* __restrict__ W2,
                                               const float* __restrict__ b2,
                                               float* __restrict__ out,
                                               int nNodes) {
    __shared__ float sW[D * 66];          // transposed weights, pitch 66
    __shared__ float sX[NODES_PB][D + 1]; // x = h + agg, reused for y
    __shared__ int   sDeg[NODES_PB];

    const int tid  = threadIdx.x;
    const int lane = tid & 31;
    const int warp = tid >> 5;
    const int half = lane >> 4;     // 0: even edges, 1: odd edges
    const int qf   = lane & 15;     // float4 index in feature row
    const int n0   = blockIdx.x * NODES_PB;
    const float4* __restrict__ h4 = (const float4*)h;

    // prefetch degrees for this block's 64 nodes, then reset counters for next replay
    if (tid < NODES_PB) {
        int node = n0 + tid;
        int dg = 0;
        if (node < nNodes) {
            dg = min(g_cnt[node], CAP);
            g_cnt[node] = 0;                 // self-reset (next replay's scatter needs zeros)
        }
        sDeg[tid] = dg;
    }

    // load W1 transposed: sW[k*66+j] = W1[j*64+k], float4 per thread
    {
        const float4* __restrict__ W14 = (const float4*)W1;
        for (int q = tid; q < (D * D) / 4; q += 256) {
            int t = q * 4;
            int j = t >> 6, k = t & 63;
            float4 w = W14[q];
            sW[(k + 0) * 66 + j] = w.x;
            sW[(k + 1) * 66 + j] = w.y;
            sW[(k + 2) * 66 + j] = w.z;
            sW[(k + 3) * 66 + j] = w.w;
        }
    }
    __syncthreads();

    // ---- Phase A: gather-max (half-warp edge-parallel) ----
#pragma unroll 1
    for (int r = 0; r < 8; r++) {
        int n = warp * 8 + r;
        int node = n0 + n;
        bool valid = node < nNodes;
        int deg = sDeg[n];
        const int off = node * CAP;
        float4 acc = make_float4(NEG_INF, NEG_INF, NEG_INF, NEG_INF);
        for (int b = 0; b < deg; b += 32) {
            int cnt = min(32, deg - b);
            int sIdx = (lane < cnt) ? g_bucket[off + b + lane] : 0;
#pragma unroll 4
            for (int e = 0; e < cnt; e += 2) {
                int e1 = (e + 1 < cnt) ? (e + 1) : e;
                int s0 = __shfl_sync(0xffffffffu, sIdx, e);
                int s1 = __shfl_sync(0xffffffffu, sIdx, e1);
                int s  = half ? s1 : s0;
                float4 v = __ldg(&h4[s * 16 + qf]);
                acc = fmax4(acc, v);
            }
        }
        acc.x = fmaxf(acc.x, __shfl_xor_sync(0xffffffffu, acc.x, 16));
        acc.y = fmaxf(acc.y, __shfl_xor_sync(0xffffffffu, acc.y, 16));
        acc.z = fmaxf(acc.z, __shfl_xor_sync(0xffffffffu, acc.z, 16));
        acc.w = fmaxf(acc.w, __shfl_xor_sync(0xffffffffu, acc.w, 16));
        if (deg == 0) acc = make_float4(0.f, 0.f, 0.f, 0.f);
        if (half == 0) {
            float4 base = valid ? __ldg(&h4[node * 16 + qf])
                                : make_float4(0.f, 0.f, 0.f, 0.f);
            sX[n][4 * qf + 0] = valid ? base.x + acc.x : 0.f;
            sX[n][4 * qf + 1] = valid ? base.y + acc.y : 0.f;
            sX[n][4 * qf + 2] = valid ? base.z + acc.z : 0.f;
            sX[n][4 * qf + 3] = valid ? base.w + acc.w : 0.f;
        }
    }
    __syncthreads();

    const int tn = (tid & 15) * 4;   // node base
    const int tj = (tid >> 4) * 4;   // output-dim base

    // ---- layer 1: y = relu(x @ W1^T), packed f32x2 ----
    unsigned long long a01[4] = {0ull, 0ull, 0ull, 0ull};
    unsigned long long a23[4] = {0ull, 0ull, 0ull, 0ull};

#pragma unroll 8
    for (int k = 0; k < D; k++) {
        const unsigned long long W01 = *(const unsigned long long*)&sW[k * 66 + tj];
        const unsigned long long W23 = *(const unsigned long long*)&sW[k * 66 + tj + 2];
#pragma unroll
        for (int nn = 0; nn < 4; nn++) {
            unsigned long long xx = dup2(sX[tn + nn][k]);
            ffma2(a01[nn], xx, W01);
            ffma2(a23[nn], xx, W23);
        }
    }
    __syncthreads();

    // y -> sX (ReLU), W2 -> sW
#pragma unroll
    for (int nn = 0; nn < 4; nn++) {
        float2 p = unpack2(a01[nn]);
        float2 q = unpack2(a23[nn]);
        sX[tn + nn][tj + 0] = fmaxf(p.x, 0.f);
        sX[tn + nn][tj + 1] = fmaxf(p.y, 0.f);
        sX[tn + nn][tj + 2] = fmaxf(q.x, 0.f);
        sX[tn + nn][tj + 3] = fmaxf(q.y, 0.f);
    }
    {
        const float4* __restrict__ W24 = (const float4*)W2;
        for (int q = tid; q < (D * D) / 4; q += 256) {
            int t = q * 4;
            int j = t >> 6, k = t & 63;
            float4 w = W24[q];
            sW[(k + 0) * 66 + j] = w.x;
            sW[(k + 1) * 66 + j] = w.y;
            sW[(k + 2) * 66 + j] = w.z;
            sW[(k + 3) * 66 + j] = w.w;
        }
    }
    __syncthreads();

    // ---- layer 2: out = y @ W2^T + b2 ----
#pragma unroll
    for (int nn = 0; nn < 4; nn++) { a01[nn] = 0ull; a23[nn] = 0ull; }

#pragma unroll 8
    for (int k = 0; k < D; k++) {
        const unsigned long long W01 = *(const unsigned long long*)&sW[k * 66 + tj];
        const unsigned long long W23 = *(const unsigned long long*)&sW[k * 66 + tj + 2];
#pragma unroll
        for (int nn = 0; nn < 4; nn++) {
            unsigned long long yy = dup2(sX[tn + nn][k]);
            ffma2(a01[nn], yy, W01);
            ffma2(a23[nn], yy, W23);
        }
    }

    float4 bias = *reinterpret_cast<const float4*>(&b2[tj]);
#pragma unroll
    for (int nn = 0; nn < 4; nn++) {
        int node = n0 + tn + nn;
        if (node < nNodes) {
            float2 p = unpack2(a01[nn]);
            float2 q = unpack2(a23[nn]);
            float4 rr;
            rr.x = p.x + bias.x;
            rr.y = p.y + bias.y;
            rr.z = q.x + bias.z;
            rr.w = q.y + bias.w;
            *reinterpret_cast<float4*>(&out[node * D + tj]) = rr;
        }
    }
}

extern "C" void kernel_launch(void* const* d_in, const int* in_sizes, int n_in,
                              void* d_out, int out_size) {
    const float* h   = (const float*)d_in[0];
    const int*   src = (const int*)d_in[1];
    const int*   dst = (const int*)d_in[2];
    const float* W1  = (const float*)d_in[3];
    const float* W2  = (const float*)d_in[4];
    const float* b2  = (const float*)d_in[5];
    float* out = (float*)d_out;

    const int nNodes = in_sizes[0] / D;
    const int E      = in_sizes[1];

    int pairs = (E + 1) / 2;
    k_scatter<<<(pairs + 255) / 256, 256>>>(src, dst, E);
    k_fused<<<(nNodes + NODES_PB - 1) / NODES_PB, 256>>>(h, W1, W2, b2, out, nNodes);
}

// round 7
// speedup vs baseline: 1.1699x; 1.1362x over previous
#include <cuda_runtime.h>
#include <cuda_bf16.h>
#include <cstdint>

// GINConv (max agg, eps=0) + MLP.
// R7: k-major swizzled activation layout -> LDS.128 conflict-free GEMM reads
// (attacks the measured 76.7% L1TEX wall). 2 launches, self-resetting counters,
// half-warp float4 gather, FFMA2 packed GEMM.
// Inputs: h[N*64] f32, src[E] i32, dst[E] i32, W1[64*64] f32, W2[64*64] f32, b2[64] f32.
// Output: out[N*64] f32.

#define D 64
#define NMAX 100000
#define CAP 96
#define NODES_PB 64
#define NEG_INF __int_as_float(0xff800000)

__device__ int g_cnt[NMAX];               // zero at load; invariant: ==0 at entry (k_fused resets)
__device__ int g_bucket[NMAX * CAP];

// ---------------- packed fp32x2 helpers (Blackwell FFMA2) ----------------
__device__ __forceinline__ void ffma2(unsigned long long& d,
                                      unsigned long long a,
                                      unsigned long long b) {
    asm("fma.rn.f32x2 %0, %1, %2, %0;" : "+l"(d) : "l"(a), "l"(b));
}
__device__ __forceinline__ unsigned long long dup2(float x) {
    unsigned long long r;
    asm("mov.b64 %0, {%1, %1};" : "=l"(r) : "f"(x));
    return r;
}
__device__ __forceinline__ float2 unpack2(unsigned long long v) {
    float2 r;
    asm("mov.b64 {%0, %1}, %2;" : "=f"(r.x), "=f"(r.y) : "l"(v));
    return r;
}

// ---------------- K1: scatter src ids into per-dst buckets ----------------
__global__ void k_scatter(const int* __restrict__ src, const int* __restrict__ dst, int E) {
    int i = blockIdx.x * blockDim.x + threadIdx.x;
    int e = i * 2;
    if (e + 1 < E) {
        int2 s = *(const int2*)&src[e];
        int2 d = *(const int2*)&dst[e];
        int p0 = atomicAdd(&g_cnt[d.x], 1);
        int p1 = atomicAdd(&g_cnt[d.y], 1);
        if (p0 < CAP) g_bucket[d.x * CAP + p0] = s.x;
        if (p1 < CAP) g_bucket[d.y * CAP + p1] = s.y;
    } else if (e < E) {
        int v = dst[e];
        int pos = atomicAdd(&g_cnt[v], 1);
        if (pos < CAP) g_bucket[v * CAP + pos] = src[e];
    }
}

__device__ __forceinline__ float4 fmax4(float4 a, float4 b) {
    a.x = fmaxf(a.x, b.x); a.y = fmaxf(a.y, b.y);
    a.z = fmaxf(a.z, b.z); a.w = fmaxf(a.w, b.w);
    return a;
}

// swizzled k-major activation address (in floats): row = feature k, col = node n
// 64 floats per row; 16B chunks XOR-permuted by (row>>2)&15.
__device__ __forceinline__ int xt_idx(int row, int col) {
    return row * 64 + ((((col >> 2) ^ ((row >> 2) & 15)) << 2) | (col & 3));
}

// ---------------- K2: fused gather-max + 2-layer MLP (+ counter reset) ----------------
__global__ __launch_bounds__(256) void k_fused(const float* __restrict__ h,
                                               const float* __restrict__ W1,
                                               const float* __restrict__ W2,
                                               const float* __restrict__ b2,
                                               float* __restrict__ out,
                                               int nNodes) {
    __shared__ float sW[D * 66];     // transposed weights, pitch 66
    __shared__ float sXT[D * 64];    // k-major swizzled activations (x, then y)
    __shared__ int   sDeg[NODES_PB];

    const int tid  = threadIdx.x;
    const int lane = tid & 31;
    const int warp = tid >> 5;
    const int half = lane >> 4;     // 0: even edges, 1: odd edges
    const int qf   = lane & 15;     // float4 index in feature row
    const int n0   = blockIdx.x * NODES_PB;
    const float4* __restrict__ h4 = (const float4*)h;

    // prefetch degrees, reset counters for next replay
    if (tid < NODES_PB) {
        int node = n0 + tid;
        int dg = 0;
        if (node < nNodes) {
            dg = min(g_cnt[node], CAP);
            g_cnt[node] = 0;
        }
        sDeg[tid] = dg;
    }

    // stage W1 transposed: sW[k*66+j] = W1[j*64+k]
    {
        const float4* __restrict__ W14 = (const float4*)W1;
        for (int q = tid; q < (D * D) / 4; q += 256) {
            int t = q * 4;
            int j = t >> 6, k = t & 63;
            float4 w = W14[q];
            sW[(k + 0) * 66 + j] = w.x;
            sW[(k + 1) * 66 + j] = w.y;
            sW[(k + 2) * 66 + j] = w.z;
            sW[(k + 3) * 66 + j] = w.w;
        }
    }
    __syncthreads();

    // ---- Phase A: gather-max (half-warp edge-parallel), write k-major ----
#pragma unroll 1
    for (int r = 0; r < 8; r++) {
        int n = warp * 8 + r;
        int node = n0 + n;
        bool valid = node < nNodes;
        int deg = sDeg[n];
        const int off = node * CAP;
        float4 acc = make_float4(NEG_INF, NEG_INF, NEG_INF, NEG_INF);
        for (int b = 0; b < deg; b += 32) {
            int cnt = min(32, deg - b);
            int sIdx = (lane < cnt) ? g_bucket[off + b + lane] : 0;
#pragma unroll 4
            for (int e = 0; e < cnt; e += 2) {
                int e1 = (e + 1 < cnt) ? (e + 1) : e;
                int s0 = __shfl_sync(0xffffffffu, sIdx, e);
                int s1 = __shfl_sync(0xffffffffu, sIdx, e1);
                int s  = half ? s1 : s0;
                float4 v = __ldg(&h4[s * 16 + qf]);
                acc = fmax4(acc, v);
            }
        }
        acc.x = fmaxf(acc.x, __shfl_xor_sync(0xffffffffu, acc.x, 16));
        acc.y = fmaxf(acc.y, __shfl_xor_sync(0xffffffffu, acc.y, 16));
        acc.z = fmaxf(acc.z, __shfl_xor_sync(0xffffffffu, acc.z, 16));
        acc.w = fmaxf(acc.w, __shfl_xor_sync(0xffffffffu, acc.w, 16));
        if (deg == 0) acc = make_float4(0.f, 0.f, 0.f, 0.f);
        if (half == 0) {
            float4 base = valid ? __ldg(&h4[node * 16 + qf])
                                : make_float4(0.f, 0.f, 0.f, 0.f);
            // features 4qf..4qf+3 of node n, rows 4qf+i: (row>>2)&15 == qf
            int ib = (4 * qf) * 64 + ((((n >> 2) ^ qf) << 2) | (n & 3));
            sXT[ib +   0] = valid ? base.x + acc.x : 0.f;
            sXT[ib +  64] = valid ? base.y + acc.y : 0.f;
            sXT[ib + 128] = valid ? base.z + acc.z : 0.f;
            sXT[ib + 192] = valid ? base.w + acc.w : 0.f;
        }
    }
    __syncthreads();

    const int tchunk = tid & 15;          // node chunk: nodes 4*tchunk..+3
    const int tn = tchunk * 4;
    const int tj = (tid >> 4) * 4;

    // ---- layer 1: y = relu(x @ W1^T), packed f32x2, LDS.128 x-reads ----
    unsigned long long a01[4] = {0ull, 0ull, 0ull, 0ull};
    unsigned long long a23[4] = {0ull, 0ull, 0ull, 0ull};

#pragma unroll 8
    for (int k = 0; k < D; k++) {
        const float4 xv = *(const float4*)&sXT[k * 64 + ((tchunk ^ ((k >> 2) & 15)) << 2)];
        const unsigned long long W01 = *(const unsigned long long*)&sW[k * 66 + tj];
        const unsigned long long W23 = *(const unsigned long long*)&sW[k * 66 + tj + 2];
        unsigned long long x0 = dup2(xv.x), x1 = dup2(xv.y);
        unsigned long long x2 = dup2(xv.z), x3 = dup2(xv.w);
        ffma2(a01[0], x0, W01); ffma2(a23[0], x0, W23);
        ffma2(a01[1], x1, W01); ffma2(a23[1], x1, W23);
        ffma2(a01[2], x2, W01); ffma2(a23[2], x2, W23);
        ffma2(a01[3], x3, W01); ffma2(a23[3], x3, W23);
    }
    __syncthreads();   // layer-1 reads of sXT/sW done

    // y -> sXT (ReLU, k-major, conflict-free STS.128), W2 -> sW
    {
        float2 p0 = unpack2(a01[0]), p1 = unpack2(a01[1]);
        float2 p2 = unpack2(a01[2]), p3 = unpack2(a01[3]);
        float2 q0 = unpack2(a23[0]), q1 = unpack2(a23[1]);
        float2 q2 = unpack2(a23[2]), q3 = unpack2(a23[3]);
        int yb = tj * 64 + ((tchunk ^ ((tj >> 2) & 15)) << 2);  // rows tj..tj+3 share (row>>2)
        *(float4*)&sXT[yb +   0] = make_float4(fmaxf(p0.x, 0.f), fmaxf(p1.x, 0.f),
                                               fmaxf(p2.x, 0.f), fmaxf(p3.x, 0.f));
        *(float4*)&sXT[yb +  64] = make_float4(fmaxf(p0.y, 0.f), fmaxf(p1.y, 0.f),
                                               fmaxf(p2.y, 0.f), fmaxf(p3.y, 0.f));
        *(float4*)&sXT[yb + 128] = make_float4(fmaxf(q0.x, 0.f), fmaxf(q1.x, 0.f),
                                               fmaxf(q2.x, 0.f), fmaxf(q3.x, 0.f));
        *(float4*)&sXT[yb + 192] = make_float4(fmaxf(q0.y, 0.f), fmaxf(q1.y, 0.f),
                                               fmaxf(q2.y, 0.f), fmaxf(q3.y, 0.f));
    }
    {
        const float4* __restrict__ W24 = (const float4*)W2;
        for (int q = tid; q < (D * D) / 4; q += 256) {
            int t = q * 4;
            int j = t >> 6, k = t & 63;
            float4 w = W24[q];
            sW[(k + 0) * 66 + j] = w.x;
            sW[(k + 1) * 66 + j] = w.y;
            sW[(k + 2) * 66 + j] = w.z;
            sW[(k + 3) * 66 + j] = w.w;
        }
    }
    __syncthreads();

    // ---- layer 2: out = y @ W2^T + b2 ----
#pragma unroll
    for (int nn = 0; nn < 4; nn++) { a01[nn] = 0ull; a23[nn] = 0ull; }

#pragma unroll 8
    for (int k = 0; k < D; k++) {
        const float4 yv = *(const float4*)&sXT[k * 64 + ((tchunk ^ ((k >> 2) & 15)) << 2)];
        const unsigned long long W01 = *(const unsigned long long*)&sW[k * 66 + tj];
        const unsigned long long W23 = *(const unsigned long long*)&sW[k * 66 + tj + 2];
        unsigned long long y0 = dup2(yv.x), y1 = dup2(yv.y);
        unsigned long long y2 = dup2(yv.z), y3 = dup2(yv.w);
        ffma2(a01[0], y0, W01); ffma2(a23[0], y0, W23);
        ffma2(a01[1], y1, W01); ffma2(a23[1], y1, W23);
        ffma2(a01[2], y2, W01); ffma2(a23[2], y2, W23);
        ffma2(a01[3], y3, W01); ffma2(a23[3], y3, W23);
    }

    float4 bias = *reinterpret_cast<const float4*>(&b2[tj]);
#pragma unroll
    for (int nn = 0; nn < 4; nn++) {
        int node = n0 + tn + nn;
        if (node < nNodes) {
            float2 p = unpack2(a01[nn]);
            float2 q = unpack2(a23[nn]);
            float4 rr;
            rr.x = p.x + bias.x;
            rr.y = p.y + bias.y;
            rr.z = q.x + bias.z;
            rr.w = q.y + bias.w;
            *reinterpret_cast<float4*>(&out[node * D + tj]) = rr;
        }
    }
}

extern "C" void kernel_launch(void* const* d_in, const int* in_sizes, int n_in,
                              void* d_out, int out_size) {
    const float* h   = (const float*)d_in[0];
    const int*   src = (const int*)d_in[1];
    const int*   dst = (const int*)d_in[2];
    const float* W1  = (const float*)d_in[3];
    const float* W2  = (const float*)d_in[4];
    const float* b2  = (const float*)d_in[5];
    float* out = (float*)d_out;

    const int nNodes = in_sizes[0] / D;
    const int E      = in_sizes[1];

    int pairs = (E + 1) / 2;
    k_scatter<<<(pairs + 255) / 256, 256>>>(src, dst, E);
    k_fused<<<(nNodes + NODES_PB - 1) / NODES_PB, 256>>>(h, W1, W2, b2, out, nNodes);
}